// round 1
// baseline (speedup 1.0000x reference)
#include <cuda_runtime.h>
#include <math.h>

// Problem constants
#define NB   256          // batch
#define NM   16           // M columns
#define LS   1024
#define LW   1024
#define LV   512
#define HH   4096         // hidden
#define KW   2048         // K of big gemm / gemm1
#define ROWS_BIG 4096     // NB*NM

// ---------------- scratch (__device__ globals: no allocation allowed) ----------------
__device__ float g_S[NB * 2048];            // [256,2048]  cos|sin features      2 MB
__device__ float g_Wcat[ROWS_BIG * KW];     // [4096,2048] transposed w feats   32 MB
__device__ float g_A0p[4 * NB * HH];        // split-K partials of S@W1top      16 MB
__device__ float g_C[NM * HH];              // v term [16,4096]                256 KB
__device__ float g_hsum[NB * HH];           // sum_m relu(...)                   4 MB
__device__ float g_etap[8 * NB * LS];       // split-K partials of hsum@W2       8 MB

// ---------------- prep: S[b, l] = cos, S[b, 1024+l] = sin, scaled 1/32 ----------------
__global__ void prep_s(const float* __restrict__ phi) {
    int i = blockIdx.x * 256 + threadIdx.x;       // 262144 total
    int b = i >> 10, l = i & 1023;
    float sv, cv;
    sincosf(phi[i], &sv, &cv);
    const float mag = 0.03125f;                   // 1/sqrt(1024)
    g_S[(b << 11) + l]        = mag * cv;
    g_S[(b << 11) + 1024 + l] = mag * sv;
}

// ---------------- transpose w_real/w_imag [B,Lw,M] -> Wcat[(b*16+m), l (+1024)] -------
__global__ void transpose_w(const float* __restrict__ wr, const float* __restrict__ wi) {
    __shared__ float s[64][17];
    int b  = blockIdx.y;
    int l0 = blockIdx.x * 64;
    const float* src = blockIdx.z ? wi : wr;
    int colbase = blockIdx.z ? 1024 : 0;
    int tid = threadIdx.x;
    const float* sp = src + (size_t)b * 16384 + (size_t)l0 * 16;
#pragma unroll
    for (int i = 0; i < 4; i++) {
        int e = tid + i * 256;                    // e = l*16 + m
        s[e >> 4][e & 15] = sp[e];
    }
    __syncthreads();
#pragma unroll
    for (int i = 0; i < 4; i++) {
        int e = tid + i * 256;
        int m = e >> 6, l = e & 63;
        g_Wcat[(size_t)(b * 16 + m) * 2048 + colbase + l0 + l] = s[l][m];
    }
}

// ---------------- C[m,h] = sum_l v_M[l,m] * W1[4096+l, h] ----------------
__global__ void compute_C(const float* __restrict__ vM, const float* __restrict__ W1) {
    __shared__ float sv[LV * NM];                 // 32 KB
    int tid = threadIdx.x;
#pragma unroll
    for (int i = 0; i < 32; i++) sv[tid + i * 256] = vM[tid + i * 256];
    __syncthreads();
    int h = blockIdx.x * 256 + tid;
    float acc[NM];
#pragma unroll
    for (int m = 0; m < NM; m++) acc[m] = 0.f;
    const float* wp = W1 + (size_t)4096 * HH + h;
    for (int l = 0; l < LV; l++) {
        float wv = wp[(size_t)l * HH];
#pragma unroll
        for (int m = 0; m < NM; m++) acc[m] = fmaf(sv[l * 16 + m], wv, acc[m]);
    }
#pragma unroll
    for (int m = 0; m < NM; m++) g_C[m * HH + h] = acc[m];
}

// ---------------- generic 128x128x16 fp32 GEMM, 256 threads, 8x8 micro ----------------
// MODE 0: A=g_S   [256,2048],  B=W1 (rows 0..2047),    out=g_A0p (split-K=4, Ksub=512)
// MODE 1: A=g_Wcat[4096,2048], B=W1+2048*4096,         fused epi -> g_hsum (K=2048)
// MODE 2: A=g_hsum[256,4096],  B=W2,                   out=g_etap (split-K=8, Ksub=512)
template <int MODE>
__global__ __launch_bounds__(256, 2)
void gemm128(const float* __restrict__ Bmat, const float* __restrict__ b1) {
    constexpr int LDA  = (MODE == 2) ? 4096 : 2048;
    constexpr int LDB  = (MODE == 2) ? 1024 : 4096;
    constexpr int NN   = (MODE == 2) ? 1024 : 4096;
    constexpr int KSUB = (MODE == 1) ? 2048 : 512;

    __shared__ float sA[16 * 128];
    __shared__ float sB[16 * 128];

    const float* A = (MODE == 0) ? g_S : (MODE == 1 ? g_Wcat : g_hsum);

    int tid = threadIdx.x;
    int tx = tid & 15, ty = tid >> 4;
    int row0 = blockIdx.y * 128;
    int col0 = blockIdx.x * 128;
    int z = blockIdx.z;

    const float* Ap = A + (size_t)z * KSUB;                 // column offset (row-major A)
    const float* Bp = Bmat + (size_t)z * KSUB * LDB;

    float acc[8][8];
#pragma unroll
    for (int i = 0; i < 8; i++)
#pragma unroll
        for (int j = 0; j < 8; j++) acc[i][j] = 0.f;

    const int ar = tid >> 1;
    const int ak = (tid & 1) * 8;
    const int bk0 = tid >> 5;               // 0..7
    const int bc  = (tid & 31) << 2;        // 0..124

    for (int k0 = 0; k0 < KSUB; k0 += 16) {
        float4 a0  = *(const float4*)(Ap + (size_t)(row0 + ar) * LDA + k0 + ak);
        float4 a1  = *(const float4*)(Ap + (size_t)(row0 + ar) * LDA + k0 + ak + 4);
        float4 b0v = *(const float4*)(Bp + (size_t)(k0 + bk0)     * LDB + col0 + bc);
        float4 b1v = *(const float4*)(Bp + (size_t)(k0 + bk0 + 8) * LDB + col0 + bc);
        __syncthreads();
        sA[(ak + 0) * 128 + ar] = a0.x;
        sA[(ak + 1) * 128 + ar] = a0.y;
        sA[(ak + 2) * 128 + ar] = a0.z;
        sA[(ak + 3) * 128 + ar] = a0.w;
        sA[(ak + 4) * 128 + ar] = a1.x;
        sA[(ak + 5) * 128 + ar] = a1.y;
        sA[(ak + 6) * 128 + ar] = a1.z;
        sA[(ak + 7) * 128 + ar] = a1.w;
        *(float4*)&sB[bk0 * 128 + bc]       = b0v;
        *(float4*)&sB[(bk0 + 8) * 128 + bc] = b1v;
        __syncthreads();
#pragma unroll
        for (int kk = 0; kk < 16; kk++) {
            float4 xa0 = *(const float4*)&sA[kk * 128 + ty * 8];
            float4 xa1 = *(const float4*)&sA[kk * 128 + ty * 8 + 4];
            float4 xb0 = *(const float4*)&sB[kk * 128 + tx * 8];
            float4 xb1 = *(const float4*)&sB[kk * 128 + tx * 8 + 4];
            float a[8] = {xa0.x, xa0.y, xa0.z, xa0.w, xa1.x, xa1.y, xa1.z, xa1.w};
            float bb[8] = {xb0.x, xb0.y, xb0.z, xb0.w, xb1.x, xb1.y, xb1.z, xb1.w};
#pragma unroll
            for (int i = 0; i < 8; i++)
#pragma unroll
                for (int j = 0; j < 8; j++) acc[i][j] = fmaf(a[i], bb[j], acc[i][j]);
        }
    }

    if (MODE == 0 || MODE == 2) {
        float* outbase = (MODE == 0) ? (g_A0p + (size_t)z * NB * HH)
                                     : (g_etap + (size_t)z * NB * LS);
#pragma unroll
        for (int i = 0; i < 8; i++) {
            float* op = outbase + (size_t)(row0 + ty * 8 + i) * NN + col0 + (tx << 3);
            *(float4*)op       = make_float4(acc[i][0], acc[i][1], acc[i][2], acc[i][3]);
            *(float4*)(op + 4) = make_float4(acc[i][4], acc[i][5], acc[i][6], acc[i][7]);
        }
    } else {
        // MODE 1 epilogue: val = acc + A0[b,h] + C[m,h] + b1[h]; relu; sum over m -> hsum
        __syncthreads();
        // stage C tile [16][128] into sB
#pragma unroll
        for (int i = 0; i < 8; i++) {
            int e = tid + i * 256;
            sB[e] = g_C[(e >> 7) * HH + col0 + (e & 127)];
        }
        __syncthreads();
        int bb_ = (row0 >> 4) + (ty >> 1);
        float av[8];
#pragma unroll
        for (int j = 0; j < 8; j++) {
            int col = col0 + (tx << 3) + j;
            float s = b1[col];
#pragma unroll
            for (int zz = 0; zz < 4; zz++) s += g_A0p[zz * (NB * HH) + bb_ * HH + col];
            av[j] = s;
        }
        float colsum[8];
#pragma unroll
        for (int j = 0; j < 8; j++) colsum[j] = 0.f;
#pragma unroll
        for (int i = 0; i < 8; i++) {
            int m = ((ty & 1) << 3) + i;
#pragma unroll
            for (int j = 0; j < 8; j++) {
                float v = acc[i][j] + av[j] + sB[m * 128 + (tx << 3) + j];
                colsum[j] += fmaxf(v, 0.f);
            }
        }
        __syncthreads();
        if (ty & 1) {
#pragma unroll
            for (int j = 0; j < 8; j++)
                sA[((((ty >> 1) << 4) + tx) << 3) + j] = colsum[j];
        }
        __syncthreads();
        if (!(ty & 1)) {
#pragma unroll
            for (int j = 0; j < 8; j++)
                g_hsum[(size_t)bb_ * HH + col0 + (tx << 3) + j] =
                    colsum[j] + sA[((((ty >> 1) << 4) + tx) << 3) + j];
        }
    }
}

// ---------------- final: out = phi - (sum_z etap + 16*b2) ----------------
__global__ void finalize_k(const float* __restrict__ phi, const float* __restrict__ b2,
                           float* __restrict__ out) {
    int i = blockIdx.x * 256 + threadIdx.x;       // 262144
    int n = i & 1023;
    float s = 0.f;
#pragma unroll
    for (int zz = 0; zz < 8; zz++) s += g_etap[zz * (NB * LS) + i];
    out[i] = phi[i] - (s + 16.0f * b2[n]);
}

extern "C" void kernel_launch(void* const* d_in, const int* in_sizes, int n_in,
                              void* d_out, int out_size) {
    const float* phi = (const float*)d_in[0];
    const float* wr  = (const float*)d_in[1];
    const float* wi  = (const float*)d_in[2];
    const float* vM  = (const float*)d_in[3];
    const float* W1  = (const float*)d_in[4];
    const float* b1  = (const float*)d_in[5];
    const float* W2  = (const float*)d_in[6];
    const float* b2  = (const float*)d_in[7];
    float* out = (float*)d_out;

    prep_s<<<1024, 256>>>(phi);
    transpose_w<<<dim3(16, 256, 2), 256>>>(wr, wi);
    compute_C<<<16, 256>>>(vM, W1);
    // A0 = S @ W1[0:2048]   (split-K = 4)
    gemm128<0><<<dim3(32, 2, 4), 256>>>(W1, nullptr);
    // hsum = sum_m relu(Wcat @ W1[2048:4096] + A0 + C + b1)
    gemm128<1><<<dim3(32, 32, 1), 256>>>(W1 + (size_t)2048 * 4096, b1);
    // etap = hsum @ W2       (split-K = 8)
    gemm128<2><<<dim3(8, 2, 8), 256>>>(W2, nullptr);
    finalize_k<<<1024, 256>>>(phi, b2, out);
}

// round 4
// speedup vs baseline: 2.2540x; 2.2540x over previous
#include <cuda_runtime.h>
#include <cstdint>
#include <math.h>

#define HH 4096

// ---------------- scratch ----------------
__device__ float g_S[256 * 2048];          //  2 MB  cos|sin (tf32-rounded)
__device__ float g_Wcat[4096 * 2048];      // 32 MB  transposed w feats (tf32)
__device__ float g_W1t[4096 * 4096];       // 64 MB  W1t[h][d] (tf32)
__device__ float g_W2t[1024 * 4096];       // 16 MB  W2t[l][h] (tf32)
__device__ float g_A0p[4 * 256 * 4096];    // 16 MB  split-K partials
__device__ float g_A0b[256 * 4096];        //  4 MB  A0 + b1
__device__ float g_C[16 * 4096];           // 256 KB v term
__device__ float g_hsum[256 * 4096];       //  4 MB  (tf32-rounded)
__device__ float g_etap[8 * 256 * 1024];   //  8 MB  split-K partials

__device__ __forceinline__ float to_tf32(float x) {
    uint32_t r;
    asm("cvt.rna.tf32.f32 %0, %1;" : "=r"(r) : "f"(x));
    return __uint_as_float(r);
}
__device__ __forceinline__ uint32_t smem_u32(const void* p) {
    uint32_t a;
    asm("{ .reg .u64 t; cvta.to.shared.u64 t, %1; cvt.u32.u64 %0, t; }" : "=r"(a) : "l"(p));
    return a;
}
#define CP16(dst, src) \
    asm volatile("cp.async.cg.shared.global [%0], [%1], 16;\n" :: "r"(dst), "l"(src))

// ======================= mma.sync tf32 GEMM =======================
// D[row0+128, col0+256] = A[128,K] @ Bt[256,K]^T ; A,Bt K-major fp32(tf32 bits).
// MODE 0: store D (+ split-K offset).  MODE 1: fused relu + sum_m -> g_hsum.
#define AST 36                       // smem row stride (floats): conflict-free
#define A_STAGE (128 * AST)
#define B_STAGE (256 * AST)
#define STAGE_FLOATS (A_STAGE + B_STAGE)
#define GEMM_SMEM (3 * STAGE_FLOATS * 4)

template <int MODE>
__global__ void __launch_bounds__(256, 1)
gemm_mma(const float* __restrict__ A, int lda,
         const float* __restrict__ Bt, int ldb,
         float* __restrict__ D, int ldd,
         int nchunks, int ksub, size_t zstride) {
    extern __shared__ float sm[];
    const int tid = threadIdx.x;
    const int row0 = blockIdx.y * 128;
    const int col0 = blockIdx.x * 256;
    const int z = blockIdx.z;

    const float* Ab = A + (size_t)z * ksub;
    const float* Bb = Bt + (size_t)z * ksub;
    const uint32_t smaddr = smem_u32(sm);

    auto load_chunk = [&](int c, int s) {
        const float* Asrc = Ab + c * 32;
        const float* Bsrc = Bb + c * 32;
        uint32_t abase = smaddr + s * (STAGE_FLOATS * 4);
        uint32_t bbase = abase + A_STAGE * 4;
#pragma unroll
        for (int i = 0; i < 4; i++) {
            int idx = tid + i * 256;
            int r = idx >> 3, sg = idx & 7;
            CP16(abase + (r * AST + sg * 4) * 4, Asrc + (size_t)(row0 + r) * lda + sg * 4);
        }
#pragma unroll
        for (int i = 0; i < 8; i++) {
            int idx = tid + i * 256;
            int r = idx >> 3, sg = idx & 7;
            CP16(bbase + (r * AST + sg * 4) * 4, Bsrc + (size_t)(col0 + r) * ldb + sg * 4);
        }
        asm volatile("cp.async.commit_group;\n");
    };

    const int wid = tid >> 5, lane = tid & 31;
    const int wm = wid & 1, wn = wid >> 1;       // 2x4 warp grid
    const int tg = lane >> 2, tir = lane & 3;

    float acc[4][8][4];
#pragma unroll
    for (int mi = 0; mi < 4; mi++)
#pragma unroll
        for (int ni = 0; ni < 8; ni++)
#pragma unroll
            for (int q = 0; q < 4; q++) acc[mi][ni][q] = 0.f;

    load_chunk(0, 0);
    load_chunk(1, 1);

    for (int c = 0; c < nchunks; c++) {
        if (c + 1 < nchunks) asm volatile("cp.async.wait_group 1;\n");
        else                 asm volatile("cp.async.wait_group 0;\n");
        __syncthreads();
        if (c + 2 < nchunks) load_chunk(c + 2, (c + 2) % 3);

        const float* sA = sm + (c % 3) * STAGE_FLOATS;
        const float* sB = sA + A_STAGE;
#pragma unroll
        for (int ks = 0; ks < 4; ks++) {
            const int kb = ks * 8;
            uint32_t af[4][4], bf[8][2];
#pragma unroll
            for (int mi = 0; mi < 4; mi++) {
                const float* p = sA + (wm * 64 + mi * 16 + tg) * AST + kb + tir;
                af[mi][0] = __float_as_uint(p[0]);
                af[mi][1] = __float_as_uint(p[8 * AST]);
                af[mi][2] = __float_as_uint(p[4]);
                af[mi][3] = __float_as_uint(p[8 * AST + 4]);
            }
#pragma unroll
            for (int ni = 0; ni < 8; ni++) {
                const float* p = sB + (wn * 64 + ni * 8 + tg) * AST + kb + tir;
                bf[ni][0] = __float_as_uint(p[0]);
                bf[ni][1] = __float_as_uint(p[4]);
            }
#pragma unroll
            for (int mi = 0; mi < 4; mi++)
#pragma unroll
                for (int ni = 0; ni < 8; ni++) {
                    asm volatile(
                        "mma.sync.aligned.m16n8k8.row.col.f32.tf32.tf32.f32 "
                        "{%0,%1,%2,%3}, {%4,%5,%6,%7}, {%8,%9}, {%0,%1,%2,%3};"
                        : "+f"(acc[mi][ni][0]), "+f"(acc[mi][ni][1]),
                          "+f"(acc[mi][ni][2]), "+f"(acc[mi][ni][3])
                        : "r"(af[mi][0]), "r"(af[mi][1]), "r"(af[mi][2]), "r"(af[mi][3]),
                          "r"(bf[ni][0]), "r"(bf[ni][1]));
                }
        }
    }

    if (MODE == 0) {
        float* Dz = D + (size_t)z * zstride;
#pragma unroll
        for (int mi = 0; mi < 4; mi++) {
            int r1 = row0 + wm * 64 + mi * 16 + tg;
#pragma unroll
            for (int ni = 0; ni < 8; ni++) {
                int cc = col0 + wn * 64 + ni * 8 + tir * 2;
                *(float2*)(Dz + (size_t)r1 * ldd + cc) =
                    make_float2(acc[mi][ni][0], acc[mi][ni][1]);
                *(float2*)(Dz + (size_t)(r1 + 8) * ldd + cc) =
                    make_float2(acc[mi][ni][2], acc[mi][ni][3]);
            }
        }
    } else {
        // fused: hsum[b][c] = sum_m relu(acc + A0b[b][c] + C[m][c])
        const int m1 = tg, m2 = tg + 8;
#pragma unroll
        for (int mi = 0; mi < 4; mi++) {
            int b = (row0 + wm * 64 + mi * 16) >> 4;
            const float* A0row = g_A0b + (size_t)b * HH;
            const float* C1 = g_C + (size_t)m1 * HH;
            const float* C2 = g_C + (size_t)m2 * HH;
#pragma unroll
            for (int ni = 0; ni < 8; ni++) {
                int cc = col0 + wn * 64 + ni * 8 + tir * 2;
                float2 a0 = *(const float2*)(A0row + cc);
                float2 c1 = *(const float2*)(C1 + cc);
                float2 c2 = *(const float2*)(C2 + cc);
                float p0 = fmaxf(acc[mi][ni][0] + a0.x + c1.x, 0.f)
                         + fmaxf(acc[mi][ni][2] + a0.x + c2.x, 0.f);
                float p1 = fmaxf(acc[mi][ni][1] + a0.y + c1.y, 0.f)
                         + fmaxf(acc[mi][ni][3] + a0.y + c2.y, 0.f);
                p0 += __shfl_down_sync(0xffffffffu, p0, 4);
                p0 += __shfl_down_sync(0xffffffffu, p0, 8);
                p0 += __shfl_down_sync(0xffffffffu, p0, 16);
                p1 += __shfl_down_sync(0xffffffffu, p1, 4);
                p1 += __shfl_down_sync(0xffffffffu, p1, 8);
                p1 += __shfl_down_sync(0xffffffffu, p1, 16);
                if (tg == 0) {
                    g_hsum[(size_t)b * HH + cc]     = to_tf32(p0);
                    g_hsum[(size_t)b * HH + cc + 1] = to_tf32(p1);
                }
            }
        }
    }
}

// ======================= small kernels =======================
__global__ void prep_s(const float* __restrict__ phi) {
    int i = blockIdx.x * 256 + threadIdx.x;
    int b = i >> 10, l = i & 1023;
    float sv, cv;
    sincosf(phi[i], &sv, &cv);
    const float mag = 0.03125f;
    g_S[(b << 11) + l]        = to_tf32(mag * cv);
    g_S[(b << 11) + 1024 + l] = to_tf32(mag * sv);
}

__global__ void transpose_w(const float* __restrict__ wr, const float* __restrict__ wi) {
    __shared__ float s[64][17];
    int b = blockIdx.y, l0 = blockIdx.x * 64;
    const float* src = blockIdx.z ? wi : wr;
    int colbase = blockIdx.z ? 1024 : 0;
    int tid = threadIdx.x;
    const float* sp = src + (size_t)b * 16384 + (size_t)l0 * 16;
#pragma unroll
    for (int i = 0; i < 4; i++) {
        int e = tid + i * 256;
        s[e >> 4][e & 15] = sp[e];
    }
    __syncthreads();
#pragma unroll
    for (int i = 0; i < 4; i++) {
        int e = tid + i * 256;
        int m = e >> 6, l = e & 63;
        g_Wcat[(size_t)(b * 16 + m) * 2048 + colbase + l0 + l] = to_tf32(s[l][m]);
    }
}

__global__ void transpose_mat(const float* __restrict__ src, float* __restrict__ dst,
                              int R, int C) {
    __shared__ float t[32][33];
    int c0 = blockIdx.x * 32, r0 = blockIdx.y * 32;
    int tx = threadIdx.x, ty = threadIdx.y;
#pragma unroll
    for (int i = 0; i < 4; i++)
        t[ty + 8 * i][tx] = src[(size_t)(r0 + ty + 8 * i) * C + c0 + tx];
    __syncthreads();
#pragma unroll
    for (int i = 0; i < 4; i++)
        dst[(size_t)(c0 + ty + 8 * i) * R + r0 + tx] = to_tf32(t[tx][ty + 8 * i]);
}

__global__ void compute_C(const float* __restrict__ vM, const float* __restrict__ W1) {
    __shared__ float sv[512 * 16];
    int tid = threadIdx.x;
#pragma unroll
    for (int i = 0; i < 32; i++) sv[tid + i * 256] = vM[tid + i * 256];
    __syncthreads();
    int h = blockIdx.x * 256 + tid;
    float acc[16];
#pragma unroll
    for (int m = 0; m < 16; m++) acc[m] = 0.f;
    const float* wp = W1 + (size_t)4096 * HH + h;
    for (int l = 0; l < 512; l++) {
        float wv = wp[(size_t)l * HH];
#pragma unroll
        for (int m = 0; m < 16; m++) acc[m] = fmaf(sv[l * 16 + m], wv, acc[m]);
    }
#pragma unroll
    for (int m = 0; m < 16; m++) g_C[m * HH + h] = acc[m];
}

__global__ void reduce_A0(const float* __restrict__ b1) {
    int i = blockIdx.x * 256 + threadIdx.x;    // 1M
    float s = b1[i & 4095];
#pragma unroll
    for (int zz = 0; zz < 4; zz++) s += g_A0p[(size_t)zz * (256 * 4096) + i];
    g_A0b[i] = s;
}

__global__ void finalize_k(const float* __restrict__ phi, const float* __restrict__ b2,
                           float* __restrict__ out) {
    int i = blockIdx.x * 256 + threadIdx.x;    // 262144
    float s = 0.f;
#pragma unroll
    for (int zz = 0; zz < 8; zz++) s += g_etap[(size_t)zz * (256 * 1024) + i];
    out[i] = phi[i] - (s + 16.0f * b2[i & 1023]);
}

// ======================= launch =======================
extern "C" void kernel_launch(void* const* d_in, const int* in_sizes, int n_in,
                              void* d_out, int out_size) {
    const float* phi = (const float*)d_in[0];
    const float* wr  = (const float*)d_in[1];
    const float* wi  = (const float*)d_in[2];
    const float* vM  = (const float*)d_in[3];
    const float* W1  = (const float*)d_in[4];
    const float* b1  = (const float*)d_in[5];
    const float* W2  = (const float*)d_in[6];
    const float* b2  = (const float*)d_in[7];
    float* out = (float*)d_out;

    cudaFuncSetAttribute(gemm_mma<0>, cudaFuncAttributeMaxDynamicSharedMemorySize, GEMM_SMEM);
    cudaFuncSetAttribute(gemm_mma<1>, cudaFuncAttributeMaxDynamicSharedMemorySize, GEMM_SMEM);

    void *pS, *pWcat, *pW1t, *pW2t, *pA0p, *pHsum, *pEtap;
    cudaGetSymbolAddress(&pS, g_S);
    cudaGetSymbolAddress(&pWcat, g_Wcat);
    cudaGetSymbolAddress(&pW1t, g_W1t);
    cudaGetSymbolAddress(&pW2t, g_W2t);
    cudaGetSymbolAddress(&pA0p, g_A0p);
    cudaGetSymbolAddress(&pHsum, g_hsum);
    cudaGetSymbolAddress(&pEtap, g_etap);

    prep_s<<<1024, 256>>>(phi);
    transpose_w<<<dim3(16, 256, 2), 256>>>(wr, wi);
    transpose_mat<<<dim3(128, 128), dim3(32, 8)>>>(W1, (float*)pW1t, 4096, 4096);
    transpose_mat<<<dim3(32, 128), dim3(32, 8)>>>(W2, (float*)pW2t, 4096, 1024);
    compute_C<<<16, 256>>>(vM, W1);

    // A0p = S @ W1[0:2048]  (split-K=4, Ksub=512 -> 16 chunks)
    gemm_mma<0><<<dim3(16, 2, 4), 256, GEMM_SMEM>>>(
        (const float*)pS, 2048, (const float*)pW1t, 4096,
        (float*)pA0p, 4096, 16, 512, (size_t)256 * 4096);
    reduce_A0<<<4096, 256>>>(b1);

    // hsum = sum_m relu(Wcat @ W1[2048:4096] + A0b + C)   (K=2048 -> 64 chunks)
    gemm_mma<1><<<dim3(16, 32, 1), 256, GEMM_SMEM>>>(
        (const float*)pWcat, 2048, (const float*)pW1t + 2048, 4096,
        nullptr, 0, 64, 0, 0);

    // etap = hsum @ W2  (split-K=8, Ksub=512 -> 16 chunks)
    gemm_mma<0><<<dim3(4, 2, 8), 256, GEMM_SMEM>>>(
        (const float*)pHsum, 4096, (const float*)pW2t, 4096,
        (float*)pEtap, 1024, 16, 512, (size_t)256 * 1024);

    finalize_k<<<1024, 256>>>(phi, b2, out);
}

// round 5
// speedup vs baseline: 2.5445x; 1.1289x over previous
#include <cuda_runtime.h>
#include <cstdint>
#include <math.h>

#define HH 4096

// ---------------- scratch ----------------
__device__ float g_S[256 * 2048];          //  2 MB  fragA order, K=2048
__device__ float g_Wcat[4096 * 2048];      // 32 MB  fragA order, K=2048
__device__ float g_W1tA[4096 * 2048];      // 32 MB  fragB order, K=2048 (d<2048)
__device__ float g_W1tB[4096 * 2048];      // 32 MB  fragB order, K=2048 (d>=2048)
__device__ float g_W2t[1024 * 4096];       // 16 MB  fragB order, K=4096
__device__ float g_A0p[4 * 256 * 4096];    // 16 MB  split-K partials (row-major)
__device__ float g_A0b[256 * 4096];        //  4 MB  A0 + b1 (row-major)
__device__ float g_C[16 * 4096];           // 256 KB v term (row-major)
__device__ float g_hsum[256 * 4096];       //  4 MB  fragA order, K=4096
__device__ float g_etap[8 * 256 * 1024];   //  8 MB  split-K partials (row-major)

__device__ __forceinline__ float to_tf32(float x) {
    uint32_t r;
    asm("cvt.rna.tf32.f32 %0, %1;" : "=r"(r) : "f"(x));
    return __uint_as_float(r);
}
__device__ __forceinline__ uint32_t smem_u32(const void* p) {
    uint32_t a;
    asm("{ .reg .u64 t; cvta.to.shared.u64 t, %1; cvt.u32.u64 %0, t; }" : "=r"(a) : "l"(p));
    return a;
}
// fragA: 512B block per 16x8 tile; lane t holds 16B = regs {a0,a1,a2,a3}
__device__ __forceinline__ size_t fragA_idx(int r, int k, int K) {
    return ((size_t)(r >> 4) * (K >> 3) + (k >> 3)) * 128
         + ((r & 7) * 4 + (k & 3)) * 4 + (((k & 4) >> 1) | ((r >> 3) & 1));
}
#define CP16(dst, src) \
    asm volatile("cp.async.cg.shared.global [%0], [%1], 16;\n" :: "r"(dst), "l"(src))

// ======================= mma.sync tf32 GEMM (fragment-ordered operands) ========
// D[row0+128, col0+256] = A[128,K] @ Bt[256,K]^T
// MODE 0: store D row-major (+split-K z offset).  MODE 1: fused relu+sum_m -> g_hsum.
#define A_STAGE 4096                  // floats (128x32 A chunk)
#define B_STAGE 8192                  // floats (256x32 B chunk)
#define STAGE_FLOATS (A_STAGE + B_STAGE)
#define GEMM_SMEM (3 * STAGE_FLOATS * 4)

template <int MODE>
__global__ void __launch_bounds__(256, 1)
gemm_mma(const float* __restrict__ A, int Ka,
         const float* __restrict__ Bt, int Kb,
         float* __restrict__ D, int ldd,
         int nchunks, int ksub, size_t zstride) {
    extern __shared__ float sm[];
    const int tid = threadIdx.x;
    const int row0 = blockIdx.y * 128;
    const int col0 = blockIdx.x * 256;
    const int z = blockIdx.z;

    const int KA8 = Ka >> 3, KB16 = Kb >> 4;
    const int kblk0 = (z * ksub) >> 3;
    const int kpblk0 = (z * ksub) >> 4;
    const int rt0 = row0 >> 4, ct0 = col0 >> 3;
    const uint32_t smaddr = smem_u32(sm);

    auto load_chunk = [&](int c, int s) {
        uint32_t abase = smaddr + s * (STAGE_FLOATS * 4);
        uint32_t bbase = abase + A_STAGE * 4;
        int kt0 = kblk0 + c * 4;
        int kp0 = kpblk0 + c * 2;
#pragma unroll
        for (int i = 0; i < 4; i++) {
            int idx = tid + i * 256;
            int blk = idx >> 5, w = idx & 31;
            const float* srcp =
                A + ((size_t)(rt0 + (blk >> 2)) * KA8 + kt0 + (blk & 3)) * 128 + w * 4;
            CP16(abase + idx * 16, srcp);
        }
#pragma unroll
        for (int i = 0; i < 8; i++) {
            int idx = tid + i * 256;
            int blk = idx >> 5, w = idx & 31;
            const float* srcp =
                Bt + ((size_t)(ct0 + (blk >> 1)) * KB16 + kp0 + (blk & 1)) * 128 + w * 4;
            CP16(bbase + idx * 16, srcp);
        }
        asm volatile("cp.async.commit_group;\n");
    };

    const int wid = tid >> 5, lane = tid & 31;
    const int wm = wid & 1, wn = wid >> 1;       // 2x4 warp grid, warp tile 64x64
    const int tg = lane >> 2, tir = lane & 3;

    float acc[4][8][4];
#pragma unroll
    for (int mi = 0; mi < 4; mi++)
#pragma unroll
        for (int ni = 0; ni < 8; ni++)
#pragma unroll
            for (int q = 0; q < 4; q++) acc[mi][ni][q] = 0.f;

    load_chunk(0, 0);
    load_chunk(1, 1);

    for (int c = 0; c < nchunks; c++) {
        if (c + 1 < nchunks) asm volatile("cp.async.wait_group 1;\n");
        else                 asm volatile("cp.async.wait_group 0;\n");
        __syncthreads();
        if (c + 2 < nchunks) load_chunk(c + 2, (c + 2) % 3);

        const float* sA = sm + (c % 3) * STAGE_FLOATS;
        const float* sB = sA + A_STAGE;
        uint4 bq[8];
#pragma unroll
        for (int ks = 0; ks < 4; ks++) {
            if ((ks & 1) == 0) {
#pragma unroll
                for (int ni = 0; ni < 8; ni++)
                    bq[ni] = *(const uint4*)(sB + (((wn * 8 + ni) * 2 + (ks >> 1)) << 7)
                                             + lane * 4);
            }
            uint4 af[4];
#pragma unroll
            for (int mi = 0; mi < 4; mi++)
                af[mi] = *(const uint4*)(sA + (((wm * 4 + mi) * 4 + ks) << 7) + lane * 4);
#pragma unroll
            for (int mi = 0; mi < 4; mi++)
#pragma unroll
                for (int ni = 0; ni < 8; ni++) {
                    uint32_t b0 = (ks & 1) ? bq[ni].z : bq[ni].x;
                    uint32_t b1 = (ks & 1) ? bq[ni].w : bq[ni].y;
                    asm volatile(
                        "mma.sync.aligned.m16n8k8.row.col.f32.tf32.tf32.f32 "
                        "{%0,%1,%2,%3}, {%4,%5,%6,%7}, {%8,%9}, {%0,%1,%2,%3};"
                        : "+f"(acc[mi][ni][0]), "+f"(acc[mi][ni][1]),
                          "+f"(acc[mi][ni][2]), "+f"(acc[mi][ni][3])
                        : "r"(af[mi].x), "r"(af[mi].y), "r"(af[mi].z), "r"(af[mi].w),
                          "r"(b0), "r"(b1));
                }
        }
    }

    if (MODE == 0) {
        float* Dz = D + (size_t)z * zstride;
#pragma unroll
        for (int mi = 0; mi < 4; mi++) {
            int r1 = row0 + wm * 64 + mi * 16 + tg;
#pragma unroll
            for (int ni = 0; ni < 8; ni++) {
                int cc = col0 + wn * 64 + ni * 8 + tir * 2;
                *(float2*)(Dz + (size_t)r1 * ldd + cc) =
                    make_float2(acc[mi][ni][0], acc[mi][ni][1]);
                *(float2*)(Dz + (size_t)(r1 + 8) * ldd + cc) =
                    make_float2(acc[mi][ni][2], acc[mi][ni][3]);
            }
        }
    } else {
        // fused: hsum[b][c] = sum_m relu(acc + A0b[b][c] + C[m][c]); fragA-order store
        const int m1 = tg, m2 = tg + 8;
#pragma unroll
        for (int mi = 0; mi < 4; mi++) {
            int b = (row0 + wm * 64 + mi * 16) >> 4;
            const float* A0row = g_A0b + (size_t)b * HH;
            const float* C1 = g_C + (size_t)m1 * HH;
            const float* C2 = g_C + (size_t)m2 * HH;
#pragma unroll
            for (int ni = 0; ni < 8; ni++) {
                int cc = col0 + wn * 64 + ni * 8 + tir * 2;
                float2 a0 = *(const float2*)(A0row + cc);
                float2 c1 = *(const float2*)(C1 + cc);
                float2 c2 = *(const float2*)(C2 + cc);
                float p0 = fmaxf(acc[mi][ni][0] + a0.x + c1.x, 0.f)
                         + fmaxf(acc[mi][ni][2] + a0.x + c2.x, 0.f);
                float p1 = fmaxf(acc[mi][ni][1] + a0.y + c1.y, 0.f)
                         + fmaxf(acc[mi][ni][3] + a0.y + c2.y, 0.f);
                p0 += __shfl_down_sync(0xffffffffu, p0, 4);
                p0 += __shfl_down_sync(0xffffffffu, p0, 8);
                p0 += __shfl_down_sync(0xffffffffu, p0, 16);
                p1 += __shfl_down_sync(0xffffffffu, p1, 4);
                p1 += __shfl_down_sync(0xffffffffu, p1, 8);
                p1 += __shfl_down_sync(0xffffffffu, p1, 16);
                if (tg == 0) {
                    g_hsum[fragA_idx(b, cc, HH)]     = to_tf32(p0);
                    g_hsum[fragA_idx(b, cc + 1, HH)] = to_tf32(p1);
                }
            }
        }
    }
}

// ======================= producers =======================
__global__ void prep_s(const float* __restrict__ phi) {
    int i = blockIdx.x * 256 + threadIdx.x;
    int b = i >> 10, l = i & 1023;
    float sv, cv;
    sincosf(phi[i], &sv, &cv);
    const float mag = 0.03125f;
    g_S[fragA_idx(b, l, 2048)]        = to_tf32(mag * cv);
    g_S[fragA_idx(b, 1024 + l, 2048)] = to_tf32(mag * sv);
}

// w_real/w_imag [B,Lw,M] -> g_Wcat fragA order (row = b*16+m, k = colbase+l)
__global__ void transpose_w(const float* __restrict__ wr, const float* __restrict__ wi) {
    __shared__ float s[64][17];
    int b = blockIdx.y, l0 = blockIdx.x * 64;
    const float* src = blockIdx.z ? wi : wr;
    int colbase = blockIdx.z ? 1024 : 0;
    int tid = threadIdx.x;
    const float* sp = src + (size_t)b * 16384 + (size_t)l0 * 16;
#pragma unroll
    for (int i = 0; i < 4; i++) {
        int e = tid + i * 256;
        s[e >> 4][e & 15] = sp[e];
    }
    __syncthreads();
    int blk = tid >> 5, t = tid & 31;            // 8 k-blocks x 32 lanes
    int m = t >> 2, kl = blk * 8 + (t & 3);
    float4 v = make_float4(to_tf32(s[kl][m]),     to_tf32(s[kl][m + 8]),
                           to_tf32(s[kl + 4][m]), to_tf32(s[kl + 4][m + 8]));
    *(float4*)(g_Wcat + ((size_t)b * 256 + (colbase + l0) / 8 + blk) * 128 + t * 4) = v;
}

// src[R,C] row-major -> fragB order dst (c = column h, k = row d), K = Kfrag
__global__ void transpose_fragB(const float* __restrict__ src, int Csrc,
                                float* __restrict__ dst, int Kfrag, int kbase) {
    __shared__ float tt[64][33];
    int h0 = blockIdx.x * 32, d0 = kbase + blockIdx.y * 64;
    int tid = threadIdx.x;
    int hl = tid & 31, dl0 = tid >> 5;
#pragma unroll
    for (int i = 0; i < 8; i++)
        tt[dl0 + i * 8][hl] = src[(size_t)(d0 + dl0 + i * 8) * Csrc + h0 + hl];
    __syncthreads();
#pragma unroll
    for (int i = 0; i < 2; i++) {
        int cid = tid + i * 256;
        int blk = cid >> 5, t = cid & 31;
        int ct = blk >> 2, kp = blk & 3;
        int cl = ct * 8 + (t >> 2), kl = kp * 16 + (t & 3);
        float4 v = make_float4(to_tf32(tt[kl][cl]),     to_tf32(tt[kl + 4][cl]),
                               to_tf32(tt[kl + 8][cl]), to_tf32(tt[kl + 12][cl]));
        *(float4*)(dst + ((size_t)(h0 / 8 + ct) * (Kfrag >> 4)
                          + (d0 - kbase) / 16 + kp) * 128 + t * 4) = v;
    }
}

__global__ void compute_C(const float* __restrict__ vM, const float* __restrict__ W1) {
    __shared__ float sv[512 * 16];
    int tid = threadIdx.x;
#pragma unroll
    for (int i = 0; i < 32; i++) sv[tid + i * 256] = vM[tid + i * 256];
    __syncthreads();
    int h = blockIdx.x * 256 + tid;
    float acc[16];
#pragma unroll
    for (int m = 0; m < 16; m++) acc[m] = 0.f;
    const float* wp = W1 + (size_t)4096 * HH + h;
    for (int l = 0; l < 512; l++) {
        float wv = wp[(size_t)l * HH];
#pragma unroll
        for (int m = 0; m < 16; m++) acc[m] = fmaf(sv[l * 16 + m], wv, acc[m]);
    }
#pragma unroll
    for (int m = 0; m < 16; m++) g_C[m * HH + h] = acc[m];
}

__global__ void reduce_A0(const float* __restrict__ b1) {
    int i = blockIdx.x * 256 + threadIdx.x;
    float s = b1[i & 4095];
#pragma unroll
    for (int zz = 0; zz < 4; zz++) s += g_A0p[(size_t)zz * (256 * 4096) + i];
    g_A0b[i] = s;
}

__global__ void finalize_k(const float* __restrict__ phi, const float* __restrict__ b2,
                           float* __restrict__ out) {
    int i = blockIdx.x * 256 + threadIdx.x;
    float s = 0.f;
#pragma unroll
    for (int zz = 0; zz < 8; zz++) s += g_etap[(size_t)zz * (256 * 1024) + i];
    out[i] = phi[i] - (s + 16.0f * b2[i & 1023]);
}

// ======================= launch =======================
extern "C" void kernel_launch(void* const* d_in, const int* in_sizes, int n_in,
                              void* d_out, int out_size) {
    const float* phi = (const float*)d_in[0];
    const float* wr  = (const float*)d_in[1];
    const float* wi  = (const float*)d_in[2];
    const float* vM  = (const float*)d_in[3];
    const float* W1  = (const float*)d_in[4];
    const float* b1  = (const float*)d_in[5];
    const float* W2  = (const float*)d_in[6];
    const float* b2  = (const float*)d_in[7];
    float* out = (float*)d_out;

    cudaFuncSetAttribute(gemm_mma<0>, cudaFuncAttributeMaxDynamicSharedMemorySize, GEMM_SMEM);
    cudaFuncSetAttribute(gemm_mma<1>, cudaFuncAttributeMaxDynamicSharedMemorySize, GEMM_SMEM);

    void *pS, *pWcat, *pW1tA, *pW1tB, *pW2t, *pA0p, *pHsum, *pEtap;
    cudaGetSymbolAddress(&pS, g_S);
    cudaGetSymbolAddress(&pWcat, g_Wcat);
    cudaGetSymbolAddress(&pW1tA, g_W1tA);
    cudaGetSymbolAddress(&pW1tB, g_W1tB);
    cudaGetSymbolAddress(&pW2t, g_W2t);
    cudaGetSymbolAddress(&pA0p, g_A0p);
    cudaGetSymbolAddress(&pHsum, g_hsum);
    cudaGetSymbolAddress(&pEtap, g_etap);

    prep_s<<<1024, 256>>>(phi);
    transpose_w<<<dim3(16, 256, 2), 256>>>(wr, wi);
    transpose_fragB<<<dim3(128, 32), 256>>>(W1, 4096, (float*)pW1tA, 2048, 0);
    transpose_fragB<<<dim3(128, 32), 256>>>(W1, 4096, (float*)pW1tB, 2048, 2048);
    transpose_fragB<<<dim3(32, 64), 256>>>(W2, 1024, (float*)pW2t, 4096, 0);
    compute_C<<<16, 256>>>(vM, W1);

    // A0p = S @ W1[0:2048]  (split-K=4)
    gemm_mma<0><<<dim3(16, 2, 4), 256, GEMM_SMEM>>>(
        (const float*)pS, 2048, (const float*)pW1tA, 2048,
        (float*)pA0p, 4096, 16, 512, (size_t)256 * 4096);
    reduce_A0<<<4096, 256>>>(b1);

    // hsum = sum_m relu(Wcat @ W1[2048:4096] + A0b + C)
    gemm_mma<1><<<dim3(16, 32, 1), 256, GEMM_SMEM>>>(
        (const float*)pWcat, 2048, (const float*)pW1tB, 2048,
        nullptr, 0, 64, 0, 0);

    // etap = hsum @ W2  (split-K=8)
    gemm_mma<0><<<dim3(4, 2, 8), 256, GEMM_SMEM>>>(
        (const float*)pHsum, 4096, (const float*)pW2t, 4096,
        (float*)pEtap, 1024, 16, 512, (size_t)256 * 1024);

    finalize_k<<<1024, 256>>>(phi, b2, out);
}

// round 6
// speedup vs baseline: 3.6719x; 1.4430x over previous
#include <cuda_runtime.h>
#include <cuda_fp16.h>
#include <cstdint>
#include <math.h>

#define HH 4096

// ---------------- scratch ----------------
__device__ __half g_S[256 * 2048];          //  1 MB  fragA order, K=2048
__device__ __half g_Wcat[4096 * 2048];      // 16 MB  fragA order, K=2048
__device__ __half g_W1tA[4096 * 2048];      // 16 MB  fragB order, K=2048 (d<2048)
__device__ __half g_W1tB[4096 * 2048];      // 16 MB  fragB order, K=2048 (d>=2048)
__device__ __half g_W2t[1024 * 4096];       //  8 MB  fragB order, K=4096
__device__ float  g_A0p[4 * 256 * 4096];    // 16 MB  split-K partials (row-major)
__device__ float  g_A0b[256 * 4096];        //  4 MB  A0 + b1 (row-major)
__device__ float  g_C[16 * 4096];           // 256 KB v term (row-major)
__device__ __half g_hsum[256 * 4096];       //  2 MB  fragA order, K=4096
__device__ float  g_etap[8 * 256 * 1024];   //  8 MB  split-K partials (row-major)

__device__ __forceinline__ uint32_t smem_u32(const void* p) {
    uint32_t a;
    asm("{ .reg .u64 t; cvta.to.shared.u64 t, %1; cvt.u32.u64 %0, t; }" : "=r"(a) : "l"(p));
    return a;
}
// fragA (m16n8k16 f16 A): 16x16 tile = 256 halves; lane t owns halves [t*8 .. t*8+7]
// element (r,k): lane=(r&7)*4+((k&7)>>1); reg=((k&8)>>2)|((r&8)>>3); half=k&1
__device__ __forceinline__ size_t fragA_half(int r, int k, int K) {
    size_t blk = (size_t)(r >> 4) * (K >> 4) + (k >> 4);
    int lane = (r & 7) * 4 + ((k & 7) >> 1);
    int reg  = ((k & 8) >> 2) | ((r & 8) >> 3);
    return blk * 256 + (size_t)((lane * 4 + reg) * 2 + (k & 1));
}
#define CP16(dst, src) \
    asm volatile("cp.async.cg.shared.global [%0], [%1], 16;\n" :: "r"(dst), "l"(src))

// ======================= mma.sync fp16 GEMM (fragment-ordered operands) ========
// D[row0+128, col0+256] = A[128,K] @ Bt[256,K]^T ; fp32 accumulate.
// MODE 0: store fp32 D row-major (+split-K z offset). MODE 1: fused relu+sum_m -> g_hsum.
#define A_STAGE_B 8192                 // bytes: 128x32 halves
#define B_STAGE_B 16384                // bytes: 256x32 halves
#define STAGE_B (A_STAGE_B + B_STAGE_B)
#define GEMM_SMEM (3 * STAGE_B)

template <int MODE>
__global__ void __launch_bounds__(256, 1)
gemm_mma(const __half* __restrict__ A, int Ka,
         const __half* __restrict__ Bt, int Kb,
         float* __restrict__ D, int ldd,
         int nchunks, int ksub, size_t zstride) {
    extern __shared__ char smc[];
    const int tid = threadIdx.x;
    const int row0 = blockIdx.y * 128;
    const int col0 = blockIdx.x * 256;
    const int z = blockIdx.z;

    const int KA16 = Ka >> 4, KB16 = Kb >> 4;
    const int ktA0 = (z * ksub) >> 4;           // base k-tile
    const int rt0 = row0 >> 4, ct0 = col0 >> 4; // row/col 16-tiles
    const uint32_t smaddr = smem_u32(smc);

    auto load_chunk = [&](int c, int s) {
        uint32_t abase = smaddr + s * STAGE_B;
        uint32_t bbase = abase + A_STAGE_B;
        int kt = ktA0 + c * 2;
#pragma unroll
        for (int i = 0; i < 2; i++) {           // A: 16 blocks x 512B
            int idx = tid + i * 256;
            int blk = idx >> 5, w = idx & 31;
            const __half* srcp =
                A + ((size_t)(rt0 + (blk >> 1)) * KA16 + kt + (blk & 1)) * 256 + w * 8;
            CP16(abase + idx * 16, srcp);
        }
#pragma unroll
        for (int i = 0; i < 4; i++) {           // B: 32 blocks x 512B
            int idx = tid + i * 256;
            int blk = idx >> 5, w = idx & 31;
            const __half* srcp =
                Bt + ((size_t)(ct0 + (blk >> 1)) * KB16 + kt + (blk & 1)) * 256 + w * 8;
            CP16(bbase + idx * 16, srcp);
        }
        asm volatile("cp.async.commit_group;\n");
    };

    const int wid = tid >> 5, lane = tid & 31;
    const int wm = wid & 1, wn = wid >> 1;       // 2x4 warp grid, warp tile 64x64
    const int tg = lane >> 2, tir = lane & 3;

    float acc[4][8][4];
#pragma unroll
    for (int mi = 0; mi < 4; mi++)
#pragma unroll
        for (int ni = 0; ni < 8; ni++)
#pragma unroll
            for (int q = 0; q < 4; q++) acc[mi][ni][q] = 0.f;

    load_chunk(0, 0);
    load_chunk(1, 1);

    for (int c = 0; c < nchunks; c++) {
        if (c + 1 < nchunks) asm volatile("cp.async.wait_group 1;\n");
        else                 asm volatile("cp.async.wait_group 0;\n");
        __syncthreads();
        if (c + 2 < nchunks) load_chunk(c + 2, (c + 2) % 3);

        const uint4* sA = (const uint4*)(smc + (c % 3) * STAGE_B);
        const uint4* sB = (const uint4*)(smc + (c % 3) * STAGE_B + A_STAGE_B);
#pragma unroll
        for (int ks = 0; ks < 2; ks++) {
            uint4 af[4], bq[4];
#pragma unroll
            for (int mi = 0; mi < 4; mi++)
                af[mi] = sA[(((wm * 4 + mi) * 2 + ks) << 5) + lane];
#pragma unroll
            for (int n2 = 0; n2 < 4; n2++)
                bq[n2] = sB[(((wn * 4 + n2) * 2 + ks) << 5) + lane];
#pragma unroll
            for (int mi = 0; mi < 4; mi++)
#pragma unroll
                for (int n2 = 0; n2 < 4; n2++) {
#pragma unroll
                    for (int nt = 0; nt < 2; nt++) {
                        int ni = n2 * 2 + nt;
                        uint32_t b0 = nt ? bq[n2].z : bq[n2].x;
                        uint32_t b1 = nt ? bq[n2].w : bq[n2].y;
                        asm volatile(
                            "mma.sync.aligned.m16n8k16.row.col.f32.f16.f16.f32 "
                            "{%0,%1,%2,%3}, {%4,%5,%6,%7}, {%8,%9}, {%0,%1,%2,%3};"
                            : "+f"(acc[mi][ni][0]), "+f"(acc[mi][ni][1]),
                              "+f"(acc[mi][ni][2]), "+f"(acc[mi][ni][3])
                            : "r"(af[mi].x), "r"(af[mi].y), "r"(af[mi].z), "r"(af[mi].w),
                              "r"(b0), "r"(b1));
                    }
                }
        }
    }

    if (MODE == 0) {
        float* Dz = D + (size_t)z * zstride;
#pragma unroll
        for (int mi = 0; mi < 4; mi++) {
            int r1 = row0 + wm * 64 + mi * 16 + tg;
#pragma unroll
            for (int ni = 0; ni < 8; ni++) {
                int cc = col0 + wn * 64 + ni * 8 + tir * 2;
                *(float2*)(Dz + (size_t)r1 * ldd + cc) =
                    make_float2(acc[mi][ni][0], acc[mi][ni][1]);
                *(float2*)(Dz + (size_t)(r1 + 8) * ldd + cc) =
                    make_float2(acc[mi][ni][2], acc[mi][ni][3]);
            }
        }
    } else {
        // fused: hsum[b][c] = sum_m relu(acc + A0b[b][c] + C[m][c]); fragA fp16 store
        const int m1 = tg, m2 = tg + 8;
#pragma unroll
        for (int mi = 0; mi < 4; mi++) {
            int b = (row0 + wm * 64 + mi * 16) >> 4;
            const float* A0row = g_A0b + (size_t)b * HH;
            const float* C1 = g_C + (size_t)m1 * HH;
            const float* C2 = g_C + (size_t)m2 * HH;
#pragma unroll
            for (int ni = 0; ni < 8; ni++) {
                int cc = col0 + wn * 64 + ni * 8 + tir * 2;
                float2 a0 = *(const float2*)(A0row + cc);
                float2 c1 = *(const float2*)(C1 + cc);
                float2 c2 = *(const float2*)(C2 + cc);
                float p0 = fmaxf(acc[mi][ni][0] + a0.x + c1.x, 0.f)
                         + fmaxf(acc[mi][ni][2] + a0.x + c2.x, 0.f);
                float p1 = fmaxf(acc[mi][ni][1] + a0.y + c1.y, 0.f)
                         + fmaxf(acc[mi][ni][3] + a0.y + c2.y, 0.f);
                p0 += __shfl_down_sync(0xffffffffu, p0, 4);
                p0 += __shfl_down_sync(0xffffffffu, p0, 8);
                p0 += __shfl_down_sync(0xffffffffu, p0, 16);
                p1 += __shfl_down_sync(0xffffffffu, p1, 4);
                p1 += __shfl_down_sync(0xffffffffu, p1, 8);
                p1 += __shfl_down_sync(0xffffffffu, p1, 16);
                if (tg == 0) {
                    size_t hi = fragA_half(b, cc, HH);   // cc even -> aligned pair
                    *(__half2*)(&g_hsum[hi]) = __floats2half2_rn(p0, p1);
                }
            }
        }
    }
}

// ======================= producers =======================
__global__ void prep_s(const float* __restrict__ phi) {
    int i = blockIdx.x * 256 + threadIdx.x;
    int b = i >> 10, l = i & 1023;
    float sv, cv;
    sincosf(phi[i], &sv, &cv);
    const float mag = 0.03125f;
    g_S[fragA_half(b, l, 2048)]        = __float2half_rn(mag * cv);
    g_S[fragA_half(b, 1024 + l, 2048)] = __float2half_rn(mag * sv);
}

// w_real/w_imag [B,Lw,M] -> g_Wcat fragA order (row = b*16+m exactly tile b)
__global__ void transpose_w(const float* __restrict__ wr, const float* __restrict__ wi) {
    __shared__ float s[64][17];
    int b = blockIdx.y, l0 = blockIdx.x * 64;
    const float* src = blockIdx.z ? wi : wr;
    int colbase = blockIdx.z ? 1024 : 0;
    int tid = threadIdx.x;
    const float* sp = src + (size_t)b * 16384 + (size_t)l0 * 16;
#pragma unroll
    for (int i = 0; i < 4; i++) {
        int e = tid + i * 256;                   // e = l*16 + m
        s[e >> 4][e & 15] = sp[e];
    }
    __syncthreads();
    // 4 k-tiles per block; each thread writes 2 consecutive words (uint2)
    int kt = tid >> 6, q0 = (tid & 63) * 2;
    uint32_t wv[2];
#pragma unroll
    for (int j = 0; j < 2; j++) {
        int q = q0 + j;
        int ln = q >> 2, rg = q & 3;
        int m = (ln >> 2) | ((rg & 1) << 3);
        int kl = kt * 16 + ((rg & 2) << 2) + (ln & 3) * 2;
        __half2 h = __floats2half2_rn(s[kl][m], s[kl + 1][m]);
        wv[j] = *(uint32_t*)&h;
    }
    uint32_t* dst = (uint32_t*)g_Wcat
        + ((size_t)b * 128 + (size_t)((colbase + l0) >> 4) + kt) * 128 + q0;
    *(uint2*)dst = make_uint2(wv[0], wv[1]);
}

// src[d][h] row-major -> fragB order dst (c = h, k = d - kbase)
__global__ void transpose_fragB(const float* __restrict__ src, int Csrc,
                                __half* __restrict__ dst, int Kfrag, int kbase) {
    __shared__ float tt[64][33];
    int h0 = blockIdx.x * 32, d0 = kbase + blockIdx.y * 64;
    int tid = threadIdx.x;
    int hl = tid & 31, dl0 = tid >> 5;
#pragma unroll
    for (int i = 0; i < 8; i++)
        tt[dl0 + i * 8][hl] = src[(size_t)(d0 + dl0 + i * 8) * Csrc + h0 + hl];
    __syncthreads();
    // 8 blocks (2 h-tiles x 4 k-tiles); thread -> one lane of one block (uint4)
    int blk = tid >> 5, ln = tid & 31;
    int ht = blk >> 2, kt = blk & 3;
    uint32_t wv[4];
#pragma unroll
    for (int nt = 0; nt < 2; nt++)
#pragma unroll
        for (int rg = 0; rg < 2; rg++) {
            int n = ht * 16 + nt * 8 + (ln >> 2);
            int k = kt * 16 + rg * 8 + (ln & 3) * 2;
            __half2 h = __floats2half2_rn(tt[k][n], tt[k + 1][n]);
            wv[nt * 2 + rg] = *(uint32_t*)&h;
        }
    uint4* dp = (uint4*)dst
        + ((size_t)((h0 >> 4) + ht) * (Kfrag >> 4) + (size_t)((d0 - kbase) >> 4) + kt) * 32
        + ln;
    *dp = make_uint4(wv[0], wv[1], wv[2], wv[3]);
}

__global__ void compute_C(const float* __restrict__ vM, const float* __restrict__ W1) {
    __shared__ float sv[512 * 16];
    int tid = threadIdx.x;
#pragma unroll
    for (int i = 0; i < 32; i++) sv[tid + i * 256] = vM[tid + i * 256];
    __syncthreads();
    int h = blockIdx.x * 256 + tid;
    float acc[16];
#pragma unroll
    for (int m = 0; m < 16; m++) acc[m] = 0.f;
    const float* wp = W1 + (size_t)4096 * HH + h;
    for (int l = 0; l < 512; l++) {
        float wv = wp[(size_t)l * HH];
#pragma unroll
        for (int m = 0; m < 16; m++) acc[m] = fmaf(sv[l * 16 + m], wv, acc[m]);
    }
#pragma unroll
    for (int m = 0; m < 16; m++) g_C[m * HH + h] = acc[m];
}

__global__ void reduce_A0(const float* __restrict__ b1) {
    int i = blockIdx.x * 256 + threadIdx.x;
    float s = b1[i & 4095];
#pragma unroll
    for (int zz = 0; zz < 4; zz++) s += g_A0p[(size_t)zz * (256 * 4096) + i];
    g_A0b[i] = s;
}

__global__ void finalize_k(const float* __restrict__ phi, const float* __restrict__ b2,
                           float* __restrict__ out) {
    int i = blockIdx.x * 256 + threadIdx.x;
    float s = 0.f;
#pragma unroll
    for (int zz = 0; zz < 8; zz++) s += g_etap[(size_t)zz * (256 * 1024) + i];
    out[i] = phi[i] - (s + 16.0f * b2[i & 1023]);
}

// ======================= launch =======================
extern "C" void kernel_launch(void* const* d_in, const int* in_sizes, int n_in,
                              void* d_out, int out_size) {
    const float* phi = (const float*)d_in[0];
    const float* wr  = (const float*)d_in[1];
    const float* wi  = (const float*)d_in[2];
    const float* vM  = (const float*)d_in[3];
    const float* W1  = (const float*)d_in[4];
    const float* b1  = (const float*)d_in[5];
    const float* W2  = (const float*)d_in[6];
    const float* b2  = (const float*)d_in[7];
    float* out = (float*)d_out;

    cudaFuncSetAttribute(gemm_mma<0>, cudaFuncAttributeMaxDynamicSharedMemorySize, GEMM_SMEM);
    cudaFuncSetAttribute(gemm_mma<1>, cudaFuncAttributeMaxDynamicSharedMemorySize, GEMM_SMEM);

    void *pS, *pWcat, *pW1tA, *pW1tB, *pW2t, *pA0p, *pHsum, *pEtap;
    cudaGetSymbolAddress(&pS, g_S);
    cudaGetSymbolAddress(&pWcat, g_Wcat);
    cudaGetSymbolAddress(&pW1tA, g_W1tA);
    cudaGetSymbolAddress(&pW1tB, g_W1tB);
    cudaGetSymbolAddress(&pW2t, g_W2t);
    cudaGetSymbolAddress(&pA0p, g_A0p);
    cudaGetSymbolAddress(&pHsum, g_hsum);
    cudaGetSymbolAddress(&pEtap, g_etap);

    // launch order puts gemm0 at slot 6 so ncu (-s 5 -c 1) profiles a GEMM
    prep_s<<<1024, 256>>>(phi);                                               // 1
    transpose_w<<<dim3(16, 256, 2), 256>>>(wr, wi);                           // 2
    transpose_fragB<<<dim3(128, 32), 256>>>(W1, 4096, (__half*)pW1tA, 2048, 0);    // 3
    transpose_fragB<<<dim3(32, 64), 256>>>(W2, 1024, (__half*)pW2t, 4096, 0);      // 4
    compute_C<<<16, 256>>>(vM, W1);                                           // 5
    // A0p = S @ W1[0:2048]  (split-K=4)                                      // 6
    gemm_mma<0><<<dim3(16, 2, 4), 256, GEMM_SMEM>>>(
        (const __half*)pS, 2048, (const __half*)pW1tA, 2048,
        (float*)pA0p, 4096, 16, 512, (size_t)256 * 4096);
    transpose_fragB<<<dim3(128, 32), 256>>>(W1, 4096, (__half*)pW1tB, 2048, 2048); // 7
    reduce_A0<<<4096, 256>>>(b1);                                             // 8
    // hsum = sum_m relu(Wcat @ W1[2048:4096] + A0b + C)
    gemm_mma<1><<<dim3(16, 32, 1), 256, GEMM_SMEM>>>(
        (const __half*)pWcat, 2048, (const __half*)pW1tB, 2048,
        nullptr, 0, 64, 0, 0);
    // etap = hsum @ W2  (split-K=8)
    gemm_mma<0><<<dim3(4, 2, 8), 256, GEMM_SMEM>>>(
        (const __half*)pHsum, 4096, (const __half*)pW2t, 4096,
        (float*)pEtap, 1024, 16, 512, (size_t)256 * 1024);
    finalize_k<<<1024, 256>>>(phi, b2, out);
}

// round 7
// speedup vs baseline: 6.2419x; 1.6999x over previous
#include <cuda_runtime.h>
#include <cuda_fp16.h>
#include <cstdint>
#include <math.h>

#define HH 4096

// ---------------- scratch ----------------
__device__ __half g_S[256 * 2048];          //  1 MB  fragA order, K=2048
__device__ __half g_Wcat[4096 * 2048];      // 16 MB  fragA order, K=2048
__device__ __half g_W1tA[4096 * 2048];      // 16 MB  fragB order, K=2048 (d<2048)
__device__ __half g_W1tB[4096 * 2048];      // 16 MB  fragB order, K=2048 (d>=2048)
__device__ __half g_W2t[1024 * 4096];       //  8 MB  fragB order, K=4096
__device__ float  g_A0p[4 * 256 * 4096];    // 16 MB  split-K partials (row-major)
__device__ float  g_A0b[256 * 4096];        //  4 MB  A0 + b1 (row-major)
__device__ float  g_C[16 * 4096];           // 256 KB v term (row-major)
__device__ __half g_hsum[256 * 4096];       //  2 MB  fragA order, K=4096
__device__ float  g_etap[8 * 256 * 1024];   //  8 MB  split-K partials (row-major)

__device__ __forceinline__ uint32_t smem_u32(const void* p) {
    uint32_t a;
    asm("{ .reg .u64 t; cvta.to.shared.u64 t, %1; cvt.u32.u64 %0, t; }" : "=r"(a) : "l"(p));
    return a;
}
// fragA (m16n8k16 f16 A): 16x16 tile = 256 halves; lane t owns halves [t*8 .. t*8+7]
__device__ __forceinline__ size_t fragA_half(int r, int k, int K) {
    size_t blk = (size_t)(r >> 4) * (K >> 4) + (k >> 4);
    int lane = (r & 7) * 4 + ((k & 7) >> 1);
    int reg  = ((k & 8) >> 2) | ((r & 8) >> 3);
    return blk * 256 + (size_t)((lane * 4 + reg) * 2 + (k & 1));
}
#define CP16(dst, src) \
    asm volatile("cp.async.cg.shared.global [%0], [%1], 16;\n" :: "r"(dst), "l"(src))

// ======================= mma.sync fp16 GEMM, tile 128x128, 2 CTA/SM ============
// D[row0+128, col0+128] = A[128,K] @ Bt[128,K]^T ; fp32 accumulate.
// MODE 0: store fp32 D row-major (+split-K z offset). MODE 1: fused relu+sum_m -> g_hsum.
#define A_STAGE_B 8192                 // bytes: 128x32 halves
#define B_STAGE_B 8192                 // bytes: 128x32 halves
#define STAGE_B (A_STAGE_B + B_STAGE_B)
#define GEMM_SMEM (3 * STAGE_B)        // 48 KB

template <int MODE>
__global__ void __launch_bounds__(256, 2)
gemm_mma(const __half* __restrict__ A, int Ka,
         const __half* __restrict__ Bt, int Kb,
         float* __restrict__ D, int ldd,
         int nchunks, int ksub, size_t zstride) {
    extern __shared__ char smc[];
    const int tid = threadIdx.x;
    const int row0 = blockIdx.y * 128;
    const int col0 = blockIdx.x * 128;
    const int z = blockIdx.z;

    const int KA16 = Ka >> 4, KB16 = Kb >> 4;
    const int ktA0 = (z * ksub) >> 4;
    const int rt0 = row0 >> 4, ct0 = col0 >> 4;
    const uint32_t smaddr = smem_u32(smc);

    auto load_chunk = [&](int c, int s) {
        uint32_t abase = smaddr + s * STAGE_B;
        uint32_t bbase = abase + A_STAGE_B;
        int kt = ktA0 + c * 2;
#pragma unroll
        for (int i = 0; i < 2; i++) {           // A: 16 blocks x 512B
            int idx = tid + i * 256;
            int blk = idx >> 5, w = idx & 31;
            const __half* srcp =
                A + ((size_t)(rt0 + (blk >> 1)) * KA16 + kt + (blk & 1)) * 256 + w * 8;
            CP16(abase + idx * 16, srcp);
        }
#pragma unroll
        for (int i = 0; i < 2; i++) {           // B: 16 blocks x 512B
            int idx = tid + i * 256;
            int blk = idx >> 5, w = idx & 31;
            const __half* srcp =
                Bt + ((size_t)(ct0 + (blk >> 1)) * KB16 + kt + (blk & 1)) * 256 + w * 8;
            CP16(bbase + idx * 16, srcp);
        }
        asm volatile("cp.async.commit_group;\n");
    };

    const int wid = tid >> 5, lane = tid & 31;
    const int wm = wid & 1, wn = wid >> 1;       // 2x4 warp grid, warp tile 64x32
    const int tg = lane >> 2, tir = lane & 3;

    float acc[4][4][4];
#pragma unroll
    for (int mi = 0; mi < 4; mi++)
#pragma unroll
        for (int ni = 0; ni < 4; ni++)
#pragma unroll
            for (int q = 0; q < 4; q++) acc[mi][ni][q] = 0.f;

    load_chunk(0, 0);
    load_chunk(1, 1);

    for (int c = 0; c < nchunks; c++) {
        if (c + 1 < nchunks) asm volatile("cp.async.wait_group 1;\n");
        else                 asm volatile("cp.async.wait_group 0;\n");
        __syncthreads();
        if (c + 2 < nchunks) load_chunk(c + 2, (c + 2) % 3);

        const uint4* sA = (const uint4*)(smc + (c % 3) * STAGE_B);
        const uint4* sB = (const uint4*)(smc + (c % 3) * STAGE_B + A_STAGE_B);
#pragma unroll
        for (int ks = 0; ks < 2; ks++) {
            uint4 af[4], bq[2];
#pragma unroll
            for (int mi = 0; mi < 4; mi++)
                af[mi] = sA[(((wm * 4 + mi) * 2 + ks) << 5) + lane];
#pragma unroll
            for (int n2 = 0; n2 < 2; n2++)
                bq[n2] = sB[(((wn * 2 + n2) * 2 + ks) << 5) + lane];
#pragma unroll
            for (int mi = 0; mi < 4; mi++)
#pragma unroll
                for (int n2 = 0; n2 < 2; n2++)
#pragma unroll
                    for (int nt = 0; nt < 2; nt++) {
                        int ni = n2 * 2 + nt;
                        uint32_t b0 = nt ? bq[n2].z : bq[n2].x;
                        uint32_t b1 = nt ? bq[n2].w : bq[n2].y;
                        asm volatile(
                            "mma.sync.aligned.m16n8k16.row.col.f32.f16.f16.f32 "
                            "{%0,%1,%2,%3}, {%4,%5,%6,%7}, {%8,%9}, {%0,%1,%2,%3};"
                            : "+f"(acc[mi][ni][0]), "+f"(acc[mi][ni][1]),
                              "+f"(acc[mi][ni][2]), "+f"(acc[mi][ni][3])
                            : "r"(af[mi].x), "r"(af[mi].y), "r"(af[mi].z), "r"(af[mi].w),
                              "r"(b0), "r"(b1));
                    }
        }
    }

    if (MODE == 0) {
        float* Dz = D + (size_t)z * zstride;
#pragma unroll
        for (int mi = 0; mi < 4; mi++) {
            int r1 = row0 + wm * 64 + mi * 16 + tg;
#pragma unroll
            for (int ni = 0; ni < 4; ni++) {
                int cc = col0 + wn * 32 + ni * 8 + tir * 2;
                *(float2*)(Dz + (size_t)r1 * ldd + cc) =
                    make_float2(acc[mi][ni][0], acc[mi][ni][1]);
                *(float2*)(Dz + (size_t)(r1 + 8) * ldd + cc) =
                    make_float2(acc[mi][ni][2], acc[mi][ni][3]);
            }
        }
    } else {
        // fused: hsum[b][c] = sum_m relu(acc + A0b[b][c] + C[m][c]); fragA fp16 store
        const int m1 = tg, m2 = tg + 8;
#pragma unroll
        for (int mi = 0; mi < 4; mi++) {
            int b = (row0 + wm * 64 + mi * 16) >> 4;
            const float* A0row = g_A0b + (size_t)b * HH;
            const float* C1 = g_C + (size_t)m1 * HH;
            const float* C2 = g_C + (size_t)m2 * HH;
#pragma unroll
            for (int ni = 0; ni < 4; ni++) {
                int cc = col0 + wn * 32 + ni * 8 + tir * 2;
                float2 a0 = *(const float2*)(A0row + cc);
                float2 c1 = *(const float2*)(C1 + cc);
                float2 c2 = *(const float2*)(C2 + cc);
                float p0 = fmaxf(acc[mi][ni][0] + a0.x + c1.x, 0.f)
                         + fmaxf(acc[mi][ni][2] + a0.x + c2.x, 0.f);
                float p1 = fmaxf(acc[mi][ni][1] + a0.y + c1.y, 0.f)
                         + fmaxf(acc[mi][ni][3] + a0.y + c2.y, 0.f);
                p0 += __shfl_down_sync(0xffffffffu, p0, 4);
                p0 += __shfl_down_sync(0xffffffffu, p0, 8);
                p0 += __shfl_down_sync(0xffffffffu, p0, 16);
                p1 += __shfl_down_sync(0xffffffffu, p1, 4);
                p1 += __shfl_down_sync(0xffffffffu, p1, 8);
                p1 += __shfl_down_sync(0xffffffffu, p1, 16);
                if (tg == 0) {
                    size_t hi = fragA_half(b, cc, HH);
                    *(__half2*)(&g_hsum[hi]) = __floats2half2_rn(p0, p1);
                }
            }
        }
    }
}

// ======================= producers =======================
__global__ void prep_s(const float* __restrict__ phi) {
    int i = blockIdx.x * 256 + threadIdx.x;
    if (i < 16 * HH) g_C[i] = 0.f;               // zero C for compute_C atomics
    int b = i >> 10, l = i & 1023;
    float sv, cv;
    sincosf(phi[i], &sv, &cv);
    const float mag = 0.03125f;
    g_S[fragA_half(b, l, 2048)]        = __float2half_rn(mag * cv);
    g_S[fragA_half(b, 1024 + l, 2048)] = __float2half_rn(mag * sv);
}

// w_real/w_imag [B,Lw,M] -> g_Wcat fragA order (row = b*16+m exactly tile b)
__global__ void transpose_w(const float* __restrict__ wr, const float* __restrict__ wi) {
    __shared__ float s[64][17];
    int b = blockIdx.y, l0 = blockIdx.x * 64;
    const float* src = blockIdx.z ? wi : wr;
    int colbase = blockIdx.z ? 1024 : 0;
    int tid = threadIdx.x;
    const float* sp = src + (size_t)b * 16384 + (size_t)l0 * 16;
#pragma unroll
    for (int i = 0; i < 4; i++) {
        int e = tid + i * 256;                   // e = l*16 + m
        s[e >> 4][e & 15] = sp[e];
    }
    __syncthreads();
    int kt = tid >> 6, q0 = (tid & 63) * 2;
    uint32_t wv[2];
#pragma unroll
    for (int j = 0; j < 2; j++) {
        int q = q0 + j;
        int ln = q >> 2, rg = q & 3;
        int m = (ln >> 2) | ((rg & 1) << 3);
        int kl = kt * 16 + ((rg & 2) << 2) + (ln & 3) * 2;
        __half2 h = __floats2half2_rn(s[kl][m], s[kl + 1][m]);
        wv[j] = *(uint32_t*)&h;
    }
    uint32_t* dst = (uint32_t*)g_Wcat
        + ((size_t)b * 128 + (size_t)((colbase + l0) >> 4) + kt) * 128 + q0;
    *(uint2*)dst = make_uint2(wv[0], wv[1]);
}

// src[d][h] row-major -> fragB order dst (c = h, k = d - kbase)
__global__ void transpose_fragB(const float* __restrict__ src, int Csrc,
                                __half* __restrict__ dst, int Kfrag, int kbase) {
    __shared__ float tt[64][33];
    int h0 = blockIdx.x * 32, d0 = kbase + blockIdx.y * 64;
    int tid = threadIdx.x;
    int hl = tid & 31, dl0 = tid >> 5;
#pragma unroll
    for (int i = 0; i < 8; i++)
        tt[dl0 + i * 8][hl] = src[(size_t)(d0 + dl0 + i * 8) * Csrc + h0 + hl];
    __syncthreads();
    int blk = tid >> 5, ln = tid & 31;
    int ht = blk >> 2, kt = blk & 3;
    uint32_t wv[4];
#pragma unroll
    for (int nt = 0; nt < 2; nt++)
#pragma unroll
        for (int rg = 0; rg < 2; rg++) {
            int n = ht * 16 + nt * 8 + (ln >> 2);
            int k = kt * 16 + rg * 8 + (ln & 3) * 2;
            __half2 h = __floats2half2_rn(tt[k][n], tt[k + 1][n]);
            wv[nt * 2 + rg] = *(uint32_t*)&h;
        }
    uint4* dp = (uint4*)dst
        + ((size_t)((h0 >> 4) + ht) * (Kfrag >> 4) + (size_t)((d0 - kbase) >> 4) + kt) * 32
        + ln;
    *dp = make_uint4(wv[0], wv[1], wv[2], wv[3]);
}

// C[m,h] += sum over l-chunk of v[l,m]*W1[4096+l,h]; grid (16 h-blocks, 8 l-chunks)
__global__ void compute_C(const float* __restrict__ vM, const float* __restrict__ W1) {
    __shared__ float sv[64 * 16];
    int tid = threadIdx.x;
    int l0 = blockIdx.y * 64;
#pragma unroll
    for (int i = 0; i < 4; i++) sv[tid + i * 256] = vM[l0 * 16 + tid + i * 256];
    __syncthreads();
    int h = blockIdx.x * 256 + tid;
    float acc[16];
#pragma unroll
    for (int m = 0; m < 16; m++) acc[m] = 0.f;
    const float* wp = W1 + (size_t)(4096 + l0) * HH + h;
    for (int l = 0; l < 64; l++) {
        float wv = wp[(size_t)l * HH];
#pragma unroll
        for (int m = 0; m < 16; m++) acc[m] = fmaf(sv[l * 16 + m], wv, acc[m]);
    }
#pragma unroll
    for (int m = 0; m < 16; m++) atomicAdd(&g_C[m * HH + h], acc[m]);
}

__global__ void reduce_A0(const float* __restrict__ b1) {
    int i = blockIdx.x * 256 + threadIdx.x;
    float s = b1[i & 4095];
#pragma unroll
    for (int zz = 0; zz < 4; zz++) s += g_A0p[(size_t)zz * (256 * 4096) + i];
    g_A0b[i] = s;
}

__global__ void finalize_k(const float* __restrict__ phi, const float* __restrict__ b2,
                           float* __restrict__ out) {
    int i = blockIdx.x * 256 + threadIdx.x;
    float s = 0.f;
#pragma unroll
    for (int zz = 0; zz < 8; zz++) s += g_etap[(size_t)zz * (256 * 1024) + i];
    out[i] = phi[i] - (s + 16.0f * b2[i & 1023]);
}

// ======================= launch =======================
extern "C" void kernel_launch(void* const* d_in, const int* in_sizes, int n_in,
                              void* d_out, int out_size) {
    const float* phi = (const float*)d_in[0];
    const float* wr  = (const float*)d_in[1];
    const float* wi  = (const float*)d_in[2];
    const float* vM  = (const float*)d_in[3];
    const float* W1  = (const float*)d_in[4];
    const float* b1  = (const float*)d_in[5];
    const float* W2  = (const float*)d_in[6];
    const float* b2  = (const float*)d_in[7];
    float* out = (float*)d_out;

    cudaFuncSetAttribute(gemm_mma<0>, cudaFuncAttributeMaxDynamicSharedMemorySize, GEMM_SMEM);
    cudaFuncSetAttribute(gemm_mma<1>, cudaFuncAttributeMaxDynamicSharedMemorySize, GEMM_SMEM);

    void *pS, *pWcat, *pW1tA, *pW1tB, *pW2t, *pA0p, *pHsum, *pEtap;
    cudaGetSymbolAddress(&pS, g_S);
    cudaGetSymbolAddress(&pWcat, g_Wcat);
    cudaGetSymbolAddress(&pW1tA, g_W1tA);
    cudaGetSymbolAddress(&pW1tB, g_W1tB);
    cudaGetSymbolAddress(&pW2t, g_W2t);
    cudaGetSymbolAddress(&pA0p, g_A0p);
    cudaGetSymbolAddress(&pHsum, g_hsum);
    cudaGetSymbolAddress(&pEtap, g_etap);

    // gemm0 at slot 6 so ncu (-s 5 -c 1) profiles a GEMM
    prep_s<<<1024, 256>>>(phi);                                                    // 1
    transpose_w<<<dim3(16, 256, 2), 256>>>(wr, wi);                                // 2
    transpose_fragB<<<dim3(128, 32), 256>>>(W1, 4096, (__half*)pW1tA, 2048, 0);    // 3
    transpose_fragB<<<dim3(32, 64), 256>>>(W2, 1024, (__half*)pW2t, 4096, 0);      // 4
    transpose_fragB<<<dim3(128, 32), 256>>>(W1, 4096, (__half*)pW1tB, 2048, 2048); // 5
    // A0p = S @ W1[0:2048]  (split-K=4)                                           // 6
    gemm_mma<0><<<dim3(32, 2, 4), 256, GEMM_SMEM>>>(
        (const __half*)pS, 2048, (const __half*)pW1tA, 2048,
        (float*)pA0p, 4096, 16, 512, (size_t)256 * 4096);
    compute_C<<<dim3(16, 8), 256>>>(vM, W1);                                       // 7
    reduce_A0<<<4096, 256>>>(b1);                                                  // 8
    // hsum = sum_m relu(Wcat @ W1[2048:4096] + A0b + C)
    gemm_mma<1><<<dim3(32, 32, 1), 256, GEMM_SMEM>>>(
        (const __half*)pWcat, 2048, (const __half*)pW1tB, 2048,
        nullptr, 0, 64, 0, 0);
    // etap = hsum @ W2  (split-K=8)
    gemm_mma<0><<<dim3(8, 2, 8), 256, GEMM_SMEM>>>(
        (const __half*)pHsum, 4096, (const __half*)pW2t, 4096,
        (float*)pEtap, 1024, 16, 512, (size_t)256 * 1024);
    finalize_k<<<1024, 256>>>(phi, b2, out);
}

// round 8
// speedup vs baseline: 6.6111x; 1.0591x over previous
#include <cuda_runtime.h>
#include <cuda_fp16.h>
#include <cstdint>
#include <math.h>

#define HH 4096

// ---------------- scratch ----------------
__device__ __half g_S[256 * 2048];          //  1 MB  fragA order, K=2048
__device__ __half g_Wcat[4096 * 2048];      // 16 MB  fragA order, K=2048
__device__ __half g_W1tA[4096 * 2048];      // 16 MB  fragB order, K=2048 (d<2048)
__device__ __half g_W1tB[4096 * 2048];      // 16 MB  fragB order, K=2048 (d>=2048)
__device__ __half g_W2t[1024 * 4096];       //  8 MB  fragB order, K=4096
__device__ float  g_A0p[4 * 256 * 4096];    // 16 MB  split-K partials (row-major)
__device__ float  g_C[16 * 4096];           // 256 KB v term (row-major)
__device__ __half g_hsum[256 * 4096];       //  2 MB  fragA order, K=4096
__device__ float  g_etap[8 * 256 * 1024];   //  8 MB  split-K partials (row-major)

__device__ __forceinline__ uint32_t smem_u32(const void* p) {
    uint32_t a;
    asm("{ .reg .u64 t; cvta.to.shared.u64 t, %1; cvt.u32.u64 %0, t; }" : "=r"(a) : "l"(p));
    return a;
}
// fragA (m16n8k16 f16 A): 16x16 tile = 256 halves; lane t owns halves [t*8 .. t*8+7]
__device__ __forceinline__ size_t fragA_half(int r, int k, int K) {
    size_t blk = (size_t)(r >> 4) * (K >> 4) + (k >> 4);
    int lane = (r & 7) * 4 + ((k & 7) >> 1);
    int reg  = ((k & 8) >> 2) | ((r & 8) >> 3);
    return blk * 256 + (size_t)((lane * 4 + reg) * 2 + (k & 1));
}
#define CP16(dst, src) \
    asm volatile("cp.async.cg.shared.global [%0], [%1], 16;\n" :: "r"(dst), "l"(src))

// ======================= mma.sync fp16 GEMM, tile 128x128, K-chunk 64 ==========
// D[row0+128, col0+128] = A[128,K] @ Bt[128,K]^T ; fp32 accumulate. 2 CTA/SM.
// MODE 0: store fp32 D row-major (+split-K z offset).
// MODE 1: fused epilogue: + (b1 + sum_z A0p) + C[m], relu, sum_m -> g_hsum (fp16 fragA).
#define A_STAGE_B 16384                // bytes: 128x64 halves
#define B_STAGE_B 16384
#define STAGE_B (A_STAGE_B + B_STAGE_B)
#define GEMM_SMEM (3 * STAGE_B)        // 96 KB

template <int MODE>
__global__ void __launch_bounds__(256, 2)
gemm_mma(const __half* __restrict__ A, int Ka,
         const __half* __restrict__ Bt, int Kb,
         float* __restrict__ D, int ldd,
         const float* __restrict__ b1,
         int nchunks, int ksub, size_t zstride) {
    extern __shared__ char smc[];
    const int tid = threadIdx.x;
    const int row0 = blockIdx.y * 128;
    const int col0 = blockIdx.x * 128;
    const int z = blockIdx.z;

    const int KA16 = Ka >> 4, KB16 = Kb >> 4;
    const int ktA0 = (z * ksub) >> 4;
    const int rt0 = row0 >> 4, ct0 = col0 >> 4;
    const uint32_t smaddr = smem_u32(smc);

    auto load_chunk = [&](int c, int s) {
        uint32_t abase = smaddr + s * STAGE_B;
        uint32_t bbase = abase + A_STAGE_B;
        int kt = ktA0 + c * 4;
#pragma unroll
        for (int i = 0; i < 4; i++) {           // A: 32 blocks x 512B
            int idx = tid + i * 256;
            int blk = idx >> 5, w = idx & 31;
            const __half* srcp =
                A + ((size_t)(rt0 + (blk >> 2)) * KA16 + kt + (blk & 3)) * 256 + w * 8;
            CP16(abase + idx * 16, srcp);
        }
#pragma unroll
        for (int i = 0; i < 4; i++) {           // B: 32 blocks x 512B
            int idx = tid + i * 256;
            int blk = idx >> 5, w = idx & 31;
            const __half* srcp =
                Bt + ((size_t)(ct0 + (blk >> 2)) * KB16 + kt + (blk & 3)) * 256 + w * 8;
            CP16(bbase + idx * 16, srcp);
        }
        asm volatile("cp.async.commit_group;\n");
    };

    const int wid = tid >> 5, lane = tid & 31;
    const int wm = wid & 1, wn = wid >> 1;       // 2x4 warp grid, warp tile 64x32
    const int tg = lane >> 2, tir = lane & 3;

    float acc[4][4][4];
#pragma unroll
    for (int mi = 0; mi < 4; mi++)
#pragma unroll
        for (int ni = 0; ni < 4; ni++)
#pragma unroll
            for (int q = 0; q < 4; q++) acc[mi][ni][q] = 0.f;

    load_chunk(0, 0);
    load_chunk(1, 1);

    for (int c = 0; c < nchunks; c++) {
        if (c + 1 < nchunks) asm volatile("cp.async.wait_group 1;\n");
        else                 asm volatile("cp.async.wait_group 0;\n");
        __syncthreads();
        if (c + 2 < nchunks) load_chunk(c + 2, (c + 2) % 3);

        const uint4* sA = (const uint4*)(smc + (c % 3) * STAGE_B);
        const uint4* sB = (const uint4*)(smc + (c % 3) * STAGE_B + A_STAGE_B);
#pragma unroll
        for (int ks = 0; ks < 4; ks++) {
            uint4 af[4], bq[2];
#pragma unroll
            for (int mi = 0; mi < 4; mi++)
                af[mi] = sA[(((wm * 4 + mi) * 4 + ks) << 5) + lane];
#pragma unroll
            for (int n2 = 0; n2 < 2; n2++)
                bq[n2] = sB[(((wn * 2 + n2) * 4 + ks) << 5) + lane];
#pragma unroll
            for (int mi = 0; mi < 4; mi++)
#pragma unroll
                for (int n2 = 0; n2 < 2; n2++)
#pragma unroll
                    for (int nt = 0; nt < 2; nt++) {
                        int ni = n2 * 2 + nt;
                        uint32_t b0 = nt ? bq[n2].z : bq[n2].x;
                        uint32_t b1r = nt ? bq[n2].w : bq[n2].y;
                        asm volatile(
                            "mma.sync.aligned.m16n8k16.row.col.f32.f16.f16.f32 "
                            "{%0,%1,%2,%3}, {%4,%5,%6,%7}, {%8,%9}, {%0,%1,%2,%3};"
                            : "+f"(acc[mi][ni][0]), "+f"(acc[mi][ni][1]),
                              "+f"(acc[mi][ni][2]), "+f"(acc[mi][ni][3])
                            : "r"(af[mi].x), "r"(af[mi].y), "r"(af[mi].z), "r"(af[mi].w),
                              "r"(b0), "r"(b1r));
                    }
        }
    }

    if (MODE == 0) {
        float* Dz = D + (size_t)z * zstride;
#pragma unroll
        for (int mi = 0; mi < 4; mi++) {
            int r1 = row0 + wm * 64 + mi * 16 + tg;
#pragma unroll
            for (int ni = 0; ni < 4; ni++) {
                int cc = col0 + wn * 32 + ni * 8 + tir * 2;
                *(float2*)(Dz + (size_t)r1 * ldd + cc) =
                    make_float2(acc[mi][ni][0], acc[mi][ni][1]);
                *(float2*)(Dz + (size_t)(r1 + 8) * ldd + cc) =
                    make_float2(acc[mi][ni][2], acc[mi][ni][3]);
            }
        }
    } else {
        // fused: hsum[b][c] = sum_m relu(acc + b1[c] + sum_z A0p[z][b][c] + C[m][c])
        const int m1 = tg, m2 = tg + 8;
#pragma unroll
        for (int mi = 0; mi < 4; mi++) {
            int b = (row0 + wm * 64 + mi * 16) >> 4;
            const float* C1 = g_C + (size_t)m1 * HH;
            const float* C2 = g_C + (size_t)m2 * HH;
#pragma unroll
            for (int ni = 0; ni < 4; ni++) {
                int cc = col0 + wn * 32 + ni * 8 + tir * 2;
                float2 a0 = *(const float2*)(b1 + cc);
#pragma unroll
                for (int zz = 0; zz < 4; zz++) {
                    float2 p = *(const float2*)(g_A0p + (size_t)zz * (256 * 4096)
                                                + (size_t)b * HH + cc);
                    a0.x += p.x; a0.y += p.y;
                }
                float2 c1 = *(const float2*)(C1 + cc);
                float2 c2 = *(const float2*)(C2 + cc);
                float p0 = fmaxf(acc[mi][ni][0] + a0.x + c1.x, 0.f)
                         + fmaxf(acc[mi][ni][2] + a0.x + c2.x, 0.f);
                float p1 = fmaxf(acc[mi][ni][1] + a0.y + c1.y, 0.f)
                         + fmaxf(acc[mi][ni][3] + a0.y + c2.y, 0.f);
                p0 += __shfl_down_sync(0xffffffffu, p0, 4);
                p0 += __shfl_down_sync(0xffffffffu, p0, 8);
                p0 += __shfl_down_sync(0xffffffffu, p0, 16);
                p1 += __shfl_down_sync(0xffffffffu, p1, 4);
                p1 += __shfl_down_sync(0xffffffffu, p1, 8);
                p1 += __shfl_down_sync(0xffffffffu, p1, 16);
                if (tg == 0) {
                    size_t hi = fragA_half(b, cc, HH);
                    *(__half2*)(&g_hsum[hi]) = __floats2half2_rn(p0, p1);
                }
            }
        }
    }
}

// ======================= producers =======================
__global__ void prep_s(const float* __restrict__ phi) {
    int i = blockIdx.x * 256 + threadIdx.x;
    if (i < 16 * HH) g_C[i] = 0.f;               // zero C for compute_C atomics
    int b = i >> 10, l = i & 1023;
    float sv, cv;
    sincosf(phi[i], &sv, &cv);
    const float mag = 0.03125f;
    g_S[fragA_half(b, l, 2048)]        = __float2half_rn(mag * cv);
    g_S[fragA_half(b, 1024 + l, 2048)] = __float2half_rn(mag * sv);
}

// w_real/w_imag [B,Lw,M] -> g_Wcat fragA order (row = b*16+m exactly tile b)
__global__ void transpose_w(const float* __restrict__ wr, const float* __restrict__ wi) {
    __shared__ float s[64][17];
    int b = blockIdx.y, l0 = blockIdx.x * 64;
    const float* src = blockIdx.z ? wi : wr;
    int colbase = blockIdx.z ? 1024 : 0;
    int tid = threadIdx.x;
    const float* sp = src + (size_t)b * 16384 + (size_t)l0 * 16;
#pragma unroll
    for (int i = 0; i < 4; i++) {
        int e = tid + i * 256;                   // e = l*16 + m
        s[e >> 4][e & 15] = sp[e];
    }
    __syncthreads();
    int kt = tid >> 6, q0 = (tid & 63) * 2;
    uint32_t wv[2];
#pragma unroll
    for (int j = 0; j < 2; j++) {
        int q = q0 + j;
        int ln = q >> 2, rg = q & 3;
        int m = (ln >> 2) | ((rg & 1) << 3);
        int kl = kt * 16 + ((rg & 2) << 2) + (ln & 3) * 2;
        __half2 h = __floats2half2_rn(s[kl][m], s[kl + 1][m]);
        wv[j] = *(uint32_t*)&h;
    }
    uint32_t* dst = (uint32_t*)g_Wcat
        + ((size_t)b * 128 + (size_t)((colbase + l0) >> 4) + kt) * 128 + q0;
    *(uint2*)dst = make_uint2(wv[0], wv[1]);
}

// src[d][h] row-major -> fragB order; blockIdx.z selects dst half + kbase
__global__ void transpose_fragB(const float* __restrict__ src, int Csrc,
                                __half* __restrict__ dst0, __half* __restrict__ dst1,
                                int Kfrag) {
    __shared__ float tt[64][33];
    __half* dst = blockIdx.z ? dst1 : dst0;
    int kbase = blockIdx.z * Kfrag;
    int h0 = blockIdx.x * 32, d0 = kbase + blockIdx.y * 64;
    int tid = threadIdx.x;
    int hl = tid & 31, dl0 = tid >> 5;
#pragma unroll
    for (int i = 0; i < 8; i++)
        tt[dl0 + i * 8][hl] = src[(size_t)(d0 + dl0 + i * 8) * Csrc + h0 + hl];
    __syncthreads();
    int blk = tid >> 5, ln = tid & 31;
    int ht = blk >> 2, kt = blk & 3;
    uint32_t wv[4];
#pragma unroll
    for (int nt = 0; nt < 2; nt++)
#pragma unroll
        for (int rg = 0; rg < 2; rg++) {
            int n = ht * 16 + nt * 8 + (ln >> 2);
            int k = kt * 16 + rg * 8 + (ln & 3) * 2;
            __half2 h = __floats2half2_rn(tt[k][n], tt[k + 1][n]);
            wv[nt * 2 + rg] = *(uint32_t*)&h;
        }
    uint4* dp = (uint4*)dst
        + ((size_t)((h0 >> 4) + ht) * (Kfrag >> 4) + (size_t)((d0 - kbase) >> 4) + kt) * 32
        + ln;
    *dp = make_uint4(wv[0], wv[1], wv[2], wv[3]);
}

// C[m,h] += sum over l-chunk of v[l,m]*W1[4096+l,h]; grid (16 h-blocks, 8 l-chunks)
__global__ void compute_C(const float* __restrict__ vM, const float* __restrict__ W1) {
    __shared__ float sv[64 * 16];
    int tid = threadIdx.x;
    int l0 = blockIdx.y * 64;
#pragma unroll
    for (int i = 0; i < 4; i++) sv[tid + i * 256] = vM[l0 * 16 + tid + i * 256];
    __syncthreads();
    int h = blockIdx.x * 256 + tid;
    float acc[16];
#pragma unroll
    for (int m = 0; m < 16; m++) acc[m] = 0.f;
    const float* wp = W1 + (size_t)(4096 + l0) * HH + h;
    for (int l = 0; l < 64; l++) {
        float wv = wp[(size_t)l * HH];
#pragma unroll
        for (int m = 0; m < 16; m++) acc[m] = fmaf(sv[l * 16 + m], wv, acc[m]);
    }
#pragma unroll
    for (int m = 0; m < 16; m++) atomicAdd(&g_C[m * HH + h], acc[m]);
}

__global__ void finalize_k(const float* __restrict__ phi, const float* __restrict__ b2,
                           float* __restrict__ out) {
    int i = blockIdx.x * 256 + threadIdx.x;
    float s = 0.f;
#pragma unroll
    for (int zz = 0; zz < 8; zz++) s += g_etap[(size_t)zz * (256 * 1024) + i];
    out[i] = phi[i] - (s + 16.0f * b2[i & 1023]);
}

// ======================= launch =======================
extern "C" void kernel_launch(void* const* d_in, const int* in_sizes, int n_in,
                              void* d_out, int out_size) {
    const float* phi = (const float*)d_in[0];
    const float* wr  = (const float*)d_in[1];
    const float* wi  = (const float*)d_in[2];
    const float* vM  = (const float*)d_in[3];
    const float* W1  = (const float*)d_in[4];
    const float* b1  = (const float*)d_in[5];
    const float* W2  = (const float*)d_in[6];
    const float* b2  = (const float*)d_in[7];
    float* out = (float*)d_out;

    cudaFuncSetAttribute(gemm_mma<0>, cudaFuncAttributeMaxDynamicSharedMemorySize, GEMM_SMEM);
    cudaFuncSetAttribute(gemm_mma<1>, cudaFuncAttributeMaxDynamicSharedMemorySize, GEMM_SMEM);

    void *pS, *pWcat, *pW1tA, *pW1tB, *pW2t, *pA0p, *pHsum, *pEtap;
    cudaGetSymbolAddress(&pS, g_S);
    cudaGetSymbolAddress(&pWcat, g_Wcat);
    cudaGetSymbolAddress(&pW1tA, g_W1tA);
    cudaGetSymbolAddress(&pW1tB, g_W1tB);
    cudaGetSymbolAddress(&pW2t, g_W2t);
    cudaGetSymbolAddress(&pA0p, g_A0p);
    cudaGetSymbolAddress(&pHsum, g_hsum);
    cudaGetSymbolAddress(&pEtap, g_etap);

    prep_s<<<1024, 256>>>(phi);                                           // idx 0
    transpose_w<<<dim3(16, 256, 2), 256>>>(wr, wi);                       // idx 1
    compute_C<<<dim3(16, 8), 256>>>(vM, W1);                              // idx 2
    transpose_fragB<<<dim3(128, 32, 2), 256>>>(                           // idx 3
        W1, 4096, (__half*)pW1tA, (__half*)pW1tB, 2048);
    // A0p = S @ W1[0:2048]  (split-K=4, ksub=512 -> 8 chunks)            // idx 4
    gemm_mma<0><<<dim3(32, 2, 4), 256, GEMM_SMEM>>>(
        (const __half*)pS, 2048, (const __half*)pW1tA, 2048,
        (float*)pA0p, 4096, nullptr, 8, 512, (size_t)256 * 4096);
    // hsum = sum_m relu(Wcat @ W1[2048:4096] + b1 + sum_z A0p + C)       // idx 5 (ncu)
    gemm_mma<1><<<dim3(32, 32, 1), 256, GEMM_SMEM>>>(
        (const __half*)pWcat, 2048, (const __half*)pW1tB, 2048,
        nullptr, 0, b1, 32, 0, 0);
    transpose_fragB<<<dim3(32, 64, 1), 256>>>(                            // idx 6
        W2, 1024, (__half*)pW2t, nullptr, 4096);
    // etap = hsum @ W2  (split-K=8, ksub=512 -> 8 chunks)                // idx 7
    gemm_mma<0><<<dim3(8, 2, 8), 256, GEMM_SMEM>>>(
        (const __half*)pHsum, 4096, (const __half*)pW2t, 4096,
        (float*)pEtap, 1024, nullptr, 8, 512, (size_t)256 * 1024);
    finalize_k<<<1024, 256>>>(phi, b2, out);                              // idx 8
}